// round 1
// baseline (speedup 1.0000x reference)
#include <cuda_runtime.h>

#define CCH 32
#define HH 48
#define WW 48
#define DDD 48
#define PD 56
#define VD 16
#define X1_CSTRIDE (48 * 48 * 48)    // 110592
#define X2P_CSTRIDE (56 * 56 * 56)   // 175616

// Zero-padded copy of x2: layout (C, 56, 56, 56), d contiguous. Zero-initialized
// at module load; pad_kernel rewrites every element each launch (deterministic).
__device__ float g_x2p[CCH * PD * PD * PD];

__global__ void pad_kernel(const float* __restrict__ x2) {
    int idx = blockIdx.x * blockDim.x + threadIdx.x;
    const int total = CCH * PD * PD * PD;
    if (idx >= total) return;
    int dp = idx % PD;
    int t = idx / PD;
    int wp = t % PD;
    t /= PD;
    int hp = t % PD;
    int c = t / PD;
    int d = dp - 4, w = wp - 4, h = hp - 4;
    float v = 0.0f;
    if ((unsigned)h < (unsigned)HH && (unsigned)w < (unsigned)WW && (unsigned)d < (unsigned)DDD)
        v = x2[((c * HH + h) * WW + w) * DDD + d];
    g_x2p[idx] = v;
}

__device__ __forceinline__ unsigned long long pk2(float lo, float hi) {
    unsigned long long r;
    asm("mov.b64 %0, {%1, %2};" : "=l"(r) : "f"(lo), "f"(hi));
    return r;
}
__device__ __forceinline__ void fma2(unsigned long long& a, unsigned long long x, unsigned long long y) {
    asm("fma.rn.f32x2 %0, %1, %2, %0;" : "+l"(a) : "l"(x), "l"(y));
}
__device__ __forceinline__ void upk2(unsigned long long v, float& lo, float& hi) {
    asm("mov.b64 {%0, %1}, %2;" : "=f"(lo), "=f"(hi) : "l"(v));
}

// Each thread: one (h, w), 16 consecutive d, one (di, dj), all 9 dk.
// acc[p][dk] is an f32x2 pair covering d voxels (2p, 2p+1).
__global__ __launch_bounds__(128, 2)
void corr_kernel(const float* __restrict__ x1, float* __restrict__ out) {
    const int dij = blockIdx.y;              // 0..80 : di*9 + dj
    const int di = dij / 9;
    const int dj = dij % 9;
    const int s = blockIdx.x * 128 + threadIdx.x;  // 0..6911
    const int d0 = (s % 3) * VD;
    const int w  = (s / 3) % WW;
    const int h  = s / (3 * WW);

    const float* p1 = x1 + ((h * WW + w) * DDD + d0);
    // x2 padded coords: hp = h+di, wp = w+dj, dp starts at d0 (covers x2 d in [d0-4, d0+19])
    const float* p2 = g_x2p + (((h + di) * PD + (w + dj)) * PD + d0);

    unsigned long long acc[8][9];
#pragma unroll
    for (int p = 0; p < 8; p++)
#pragma unroll
        for (int k = 0; k < 9; k++) acc[p][k] = 0ull;

#pragma unroll 1
    for (int c = 0; c < CCH; c++) {
        float4 a0 = *(const float4*)(p1 + 0);
        float4 a1 = *(const float4*)(p1 + 4);
        float4 a2 = *(const float4*)(p1 + 8);
        float4 a3 = *(const float4*)(p1 + 12);
        float4 b0 = *(const float4*)(p2 + 0);
        float4 b1 = *(const float4*)(p2 + 4);
        float4 b2 = *(const float4*)(p2 + 8);
        float4 b3 = *(const float4*)(p2 + 12);
        float4 b4 = *(const float4*)(p2 + 16);
        float4 b5 = *(const float4*)(p2 + 20);
        p1 += X1_CSTRIDE;
        p2 += X2P_CSTRIDE;

        unsigned long long A[8];
        A[0] = pk2(a0.x, a0.y); A[1] = pk2(a0.z, a0.w);
        A[2] = pk2(a1.x, a1.y); A[3] = pk2(a1.z, a1.w);
        A[4] = pk2(a2.x, a2.y); A[5] = pk2(a2.z, a2.w);
        A[6] = pk2(a3.x, a3.y); A[7] = pk2(a3.z, a3.w);

        const float e[24] = { b0.x, b0.y, b0.z, b0.w,
                              b1.x, b1.y, b1.z, b1.w,
                              b2.x, b2.y, b2.z, b2.w,
                              b3.x, b3.y, b3.z, b3.w,
                              b4.x, b4.y, b4.z, b4.w,
                              b5.x, b5.y, b5.z, b5.w };

        unsigned long long P[12];   // P[j] = (e[2j], e[2j+1])   -> even dk
        unsigned long long S[11];   // S[j] = (e[2j+1], e[2j+2]) -> odd dk
#pragma unroll
        for (int j = 0; j < 12; j++) P[j] = pk2(e[2 * j], e[2 * j + 1]);
#pragma unroll
        for (int j = 0; j < 11; j++) S[j] = pk2(e[2 * j + 1], e[2 * j + 2]);

#pragma unroll
        for (int p = 0; p < 8; p++) {
#pragma unroll
            for (int dk = 0; dk < 9; dk++) {
                // b pair starts at local x2 index 2p + dk
                if (dk & 1) fma2(acc[p][dk], A[p], S[p + (dk >> 1)]);
                else        fma2(acc[p][dk], A[p], P[p + (dk >> 1)]);
            }
        }
    }

    const float inv = 1.0f / 32.0f;   // mean over channels
    const size_t obase = (size_t)(h * WW + w) * DDD + d0;
#pragma unroll
    for (int dk = 0; dk < 9; dk++) {
        float* dst = out + (size_t)(dij * 9 + dk) * X1_CSTRIDE + obase;
#pragma unroll
        for (int q = 0; q < 4; q++) {
            float l0, h0, l1, h1;
            upk2(acc[2 * q][dk], l0, h0);
            upk2(acc[2 * q + 1][dk], l1, h1);
            *(float4*)(dst + 4 * q) = make_float4(l0 * inv, h0 * inv, l1 * inv, h1 * inv);
        }
    }
}

extern "C" void kernel_launch(void* const* d_in, const int* in_sizes, int n_in,
                              void* d_out, int out_size) {
    const float* x1 = (const float*)d_in[0];
    const float* x2 = (const float*)d_in[1];
    float* out = (float*)d_out;

    const int total = CCH * PD * PD * PD;
    pad_kernel<<<(total + 255) / 256, 256>>>(x2);

    dim3 grid(54, 81);   // 54*128 = 6912 spatial segments, 81 (di,dj) groups
    corr_kernel<<<grid, 128>>>(x1, out);
}

// round 2
// speedup vs baseline: 2.0986x; 2.0986x over previous
#include <cuda_runtime.h>

#define CCH 32
#define HH 48
#define WW 48
#define DDD 48
#define PD 56
#define VD 8
#define X1_CSTRIDE (48 * 48 * 48)    // 110592
#define X2P_CSTRIDE (56 * 56 * 56)   // 175616

// Zero-padded copy of x2: layout (C, 56, 56, 56), d contiguous.
__device__ float g_x2p[CCH * PD * PD * PD];

__global__ void pad_kernel(const float* __restrict__ x2) {
    int idx = blockIdx.x * blockDim.x + threadIdx.x;
    const int total = CCH * PD * PD * PD;
    if (idx >= total) return;
    int dp = idx % PD;
    int t = idx / PD;
    int wp = t % PD;
    t /= PD;
    int hp = t % PD;
    int c = t / PD;
    int d = dp - 4, w = wp - 4, h = hp - 4;
    float v = 0.0f;
    if ((unsigned)h < (unsigned)HH && (unsigned)w < (unsigned)WW && (unsigned)d < (unsigned)DDD)
        v = x2[((c * HH + h) * WW + w) * DDD + d];
    g_x2p[idx] = v;
}

__device__ __forceinline__ unsigned long long pk2(float lo, float hi) {
    unsigned long long r;
    asm("mov.b64 %0, {%1, %2};" : "=l"(r) : "f"(lo), "f"(hi));
    return r;
}
__device__ __forceinline__ void fma2(unsigned long long& a, unsigned long long x, unsigned long long y) {
    asm("fma.rn.f32x2 %0, %1, %2, %0;" : "+l"(a) : "l"(x), "l"(y));
}
__device__ __forceinline__ void upk2(unsigned long long v, float& lo, float& hi) {
    asm("mov.b64 {%0, %1}, %2;" : "=f"(lo), "=f"(hi) : "l"(v));
}

// Each thread: one (h, w), 8 consecutive d, one (di, dj), all 9 dk.
// acc[p][dk] is an f32x2 pair covering output d voxels (d0+2p, d0+2p+1).
__global__ __launch_bounds__(128, 3)
void corr_kernel(const float* __restrict__ x1, float* __restrict__ out) {
    const int dij = blockIdx.y;              // 0..80 : di*9 + dj
    const int di = dij / 9;
    const int dj = dij % 9;
    const int s = blockIdx.x * 128 + threadIdx.x;  // 0..13823
    const int d0 = (s % 6) * VD;
    const int w  = (s / 6) % WW;
    const int h  = s / (6 * WW);

    const float* p1 = x1 + ((h * WW + w) * DDD + d0);
    // padded d index d0 corresponds to unpadded d0-4; window = 16 floats
    const float* p2 = g_x2p + (((h + di) * PD + (w + dj)) * PD + d0);

    unsigned long long acc[4][9];
#pragma unroll
    for (int p = 0; p < 4; p++)
#pragma unroll
        for (int k = 0; k < 9; k++) acc[p][k] = 0ull;

#pragma unroll 1
    for (int c = 0; c < CCH; c++) {
        float4 a0 = *(const float4*)(p1 + 0);
        float4 a1 = *(const float4*)(p1 + 4);
        float4 b0 = *(const float4*)(p2 + 0);
        float4 b1 = *(const float4*)(p2 + 4);
        float4 b2 = *(const float4*)(p2 + 8);
        float4 b3 = *(const float4*)(p2 + 12);
        p1 += X1_CSTRIDE;
        p2 += X2P_CSTRIDE;

        unsigned long long A[4];
        A[0] = pk2(a0.x, a0.y); A[1] = pk2(a0.z, a0.w);
        A[2] = pk2(a1.x, a1.y); A[3] = pk2(a1.z, a1.w);

        // aligned pairs (even dk): P[j] = (e[2j], e[2j+1])
        unsigned long long P[8];
        P[0] = pk2(b0.x, b0.y); P[1] = pk2(b0.z, b0.w);
        P[2] = pk2(b1.x, b1.y); P[3] = pk2(b1.z, b1.w);
        P[4] = pk2(b2.x, b2.y); P[5] = pk2(b2.z, b2.w);
        P[6] = pk2(b3.x, b3.y); P[7] = pk2(b3.z, b3.w);
        // shifted pairs (odd dk): S[j] = (e[2j+1], e[2j+2])
        unsigned long long S[7];
        S[0] = pk2(b0.y, b0.z); S[1] = pk2(b0.w, b1.x);
        S[2] = pk2(b1.y, b1.z); S[3] = pk2(b1.w, b2.x);
        S[4] = pk2(b2.y, b2.z); S[5] = pk2(b2.w, b3.x);
        S[6] = pk2(b3.y, b3.z);

#pragma unroll
        for (int p = 0; p < 4; p++) {
#pragma unroll
            for (int dk = 0; dk < 9; dk++) {
                // b pair starts at local x2 index 2p + dk
                if (dk & 1) fma2(acc[p][dk], A[p], S[p + (dk >> 1)]);
                else        fma2(acc[p][dk], A[p], P[p + (dk >> 1)]);
            }
        }
    }

    const float inv = 1.0f / 32.0f;   // mean over channels
    const size_t obase = (size_t)(h * WW + w) * DDD + d0;
#pragma unroll
    for (int dk = 0; dk < 9; dk++) {
        float* dst = out + (size_t)(dij * 9 + dk) * X1_CSTRIDE + obase;
        float l0, h0, l1, h1;
        upk2(acc[0][dk], l0, h0);
        upk2(acc[1][dk], l1, h1);
        *(float4*)(dst + 0) = make_float4(l0 * inv, h0 * inv, l1 * inv, h1 * inv);
        upk2(acc[2][dk], l0, h0);
        upk2(acc[3][dk], l1, h1);
        *(float4*)(dst + 4) = make_float4(l0 * inv, h0 * inv, l1 * inv, h1 * inv);
    }
}

extern "C" void kernel_launch(void* const* d_in, const int* in_sizes, int n_in,
                              void* d_out, int out_size) {
    const float* x1 = (const float*)d_in[0];
    const float* x2 = (const float*)d_in[1];
    float* out = (float*)d_out;

    const int total = CCH * PD * PD * PD;
    pad_kernel<<<(total + 255) / 256, 256>>>(x2);

    dim3 grid(108, 81);   // 108*128 = 13824 spatial segments, 81 (di,dj) groups
    corr_kernel<<<grid, 128>>>(x1, out);
}